// round 4
// baseline (speedup 1.0000x reference)
#include <cuda_runtime.h>
#include <math.h>

// ---------------- problem constants ----------------
#define LNUM 2
#define BB   4
#define TT   1000
#define CC   768
#define HH   12
#define DKK  64
#define WHALF 50         // band half-width (WIN//2)
#define NR   101         // relative positions actually reachable: -50..50
#define BT   (BB*TT)     // 4000 rows

// ---------------- device scratch (no allocs allowed) ----------------
__device__ float g_h[BT*CC];
__device__ float g_y[BT*CC];
__device__ float g_q[BT*CC];
__device__ float g_k[BT*CC];
__device__ float g_v[BT*CC];
__device__ float g_o[BT*CC];
__device__ float g_pe[NR*CC];   // central 101 rows of the rel-pos table
__device__ float g_pc[NR*CC];   // pe_cen @ Wp[l]

// ---------------- init: h = x * sqrt(C) ----------------
__global__ void init_h_kernel(const float* __restrict__ x) {
    int i = blockIdx.x * blockDim.x + threadIdx.x;
    if (i < BT*CC) g_h[i] = x[i] * 27.712812921102035f;  // sqrt(768)
}

// ---------------- positional table (central 101 rows only) ----------------
// pe row index jg = T-1 + delta, rel = (T-1) - jg = -delta, delta = r-50
// pe[r][2j]   = sin(rel * div_j),  pe[r][2j+1] = cos(rel * div_j)
__global__ void pe_kernel() {
    int i = blockIdx.x * blockDim.x + threadIdx.x;
    if (i < NR*(CC/2)) {
        int r = i / (CC/2);
        int j = i % (CC/2);
        float div = expf(-(float)(2*j) * (9.210340371976184f / (float)CC)); // ln(10000)/C
        float ang = (float)(WHALF - r) * div;   // rel = -(r-50)
        g_pe[r*CC + 2*j]     = sinf(ang);
        g_pe[r*CC + 2*j + 1] = cosf(ang);
    }
}

// ---------------- LayerNorm (one block per row) ----------------
__global__ void ln_kernel(const float* __restrict__ in, float* __restrict__ out,
                          const float* __restrict__ g, const float* __restrict__ b) {
    int row = blockIdx.x;
    const float* xr = in + (size_t)row * CC;
    float s = 0.f, s2 = 0.f;
    for (int i = threadIdx.x; i < CC; i += 256) {
        float v = xr[i];
        s += v; s2 += v * v;
    }
    __shared__ float sh[16];
    #pragma unroll
    for (int o = 16; o; o >>= 1) {
        s  += __shfl_xor_sync(0xffffffffu, s,  o);
        s2 += __shfl_xor_sync(0xffffffffu, s2, o);
    }
    int w = threadIdx.x >> 5;
    if ((threadIdx.x & 31) == 0) { sh[w] = s; sh[8 + w] = s2; }
    __syncthreads();
    s = 0.f; s2 = 0.f;
    #pragma unroll
    for (int i = 0; i < 8; i++) { s += sh[i]; s2 += sh[8 + i]; }
    float mean = s * (1.f / CC);
    float var  = s2 * (1.f / CC) - mean * mean;
    float rstd = rsqrtf(var + 1e-5f);
    float* orow = out + (size_t)row * CC;
    for (int i = threadIdx.x; i < CC; i += 256)
        orow[i] = (xr[i] - mean) * rstd * g[i] + b[i];
}

// ---------------- SGEMM: C = A(MxK) @ B(KxN) [+bias] [epilogue] ----------------
// BM=128, BN=64, BK=16, 256 threads, 8x4 register tile.
// EPI: 0 = none, 1 = gelu(tanh approx), 2 = += resid
#define GBM 128
#define GBN 64
#define GBK 16
#define ASTR 132   // padded A-tile row stride (floats), 16B-aligned rows

__device__ __forceinline__ float gelu_f(float x) {
    float x3 = x * x * x;
    return 0.5f * x * (1.f + tanhf(0.7978845608028654f * (x + 0.044715f * x3)));
}

template<int EPI>
__global__ void __launch_bounds__(256)
sgemm_kernel(const float* __restrict__ A, const float* __restrict__ Bm,
             const float* __restrict__ bias, const float* __restrict__ resid,
             float* __restrict__ Cm, int M, int N, int K) {
    __shared__ __align__(16) float As[GBK * ASTR];
    __shared__ __align__(16) float Bs[GBK][GBN];
    int tid = threadIdx.x;
    int tx = tid & 15;        // 0..15  -> 4 cols
    int ty = tid >> 4;        // 0..15  -> 8 rows
    int row0 = blockIdx.y * GBM;
    int col0 = blockIdx.x * GBN;

    float acc[8][4];
    #pragma unroll
    for (int i = 0; i < 8; i++)
        #pragma unroll
        for (int j = 0; j < 4; j++) acc[i][j] = 0.f;

    int ar = tid >> 2;            // 0..63
    int ac = (tid & 3) * 4;       // 0,4,8,12
    int br = tid >> 4;            // 0..15
    int bc = (tid & 15) * 4;      // 0..60

    for (int k0 = 0; k0 < K; k0 += GBK) {
        // A tile: 128x16, transposed into As[k][m]
        #pragma unroll
        for (int half = 0; half < 2; half++) {
            int m  = ar + half * 64;
            int gr = row0 + m;
            float4 av = make_float4(0.f, 0.f, 0.f, 0.f);
            if (gr < M) av = *(const float4*)(A + (size_t)gr * K + k0 + ac);
            As[(ac + 0) * ASTR + m] = av.x;
            As[(ac + 1) * ASTR + m] = av.y;
            As[(ac + 2) * ASTR + m] = av.z;
            As[(ac + 3) * ASTR + m] = av.w;
        }
        // B tile: 16x64 (K,N row-major; K%16==0, N%64==0 always here)
        *(float4*)&Bs[br][bc] = *(const float4*)(Bm + (size_t)(k0 + br) * N + col0 + bc);
        __syncthreads();

        #pragma unroll
        for (int kk = 0; kk < GBK; kk++) {
            float4 a0 = *(const float4*)&As[kk * ASTR + ty * 8];
            float4 a1 = *(const float4*)&As[kk * ASTR + ty * 8 + 4];
            float4 bq = *(const float4*)&Bs[kk][tx * 4];
            float am[8] = {a0.x, a0.y, a0.z, a0.w, a1.x, a1.y, a1.z, a1.w};
            float bn[4] = {bq.x, bq.y, bq.z, bq.w};
            #pragma unroll
            for (int i = 0; i < 8; i++)
                #pragma unroll
                for (int j = 0; j < 4; j++) acc[i][j] += am[i] * bn[j];
        }
        __syncthreads();
    }

    float4 bv = make_float4(0.f, 0.f, 0.f, 0.f);
    if (bias) bv = *(const float4*)(bias + col0 + tx * 4);
    #pragma unroll
    for (int i = 0; i < 8; i++) {
        int gr = row0 + ty * 8 + i;
        if (gr >= M) continue;
        float c0 = acc[i][0] + bv.x, c1 = acc[i][1] + bv.y;
        float c2 = acc[i][2] + bv.z, c3 = acc[i][3] + bv.w;
        if (EPI == 1) { c0 = gelu_f(c0); c1 = gelu_f(c1); c2 = gelu_f(c2); c3 = gelu_f(c3); }
        if (EPI == 2) {
            float4 rv = *(const float4*)(resid + (size_t)gr * N + col0 + tx * 4);
            c0 += rv.x; c1 += rv.y; c2 += rv.z; c3 += rv.w;
        }
        *(float4*)(Cm + (size_t)gr * N + col0 + tx * 4) = make_float4(c0, c1, c2, c3);
    }
}

// ---------------- banded rel-pos attention ----------------
// One block: (b, h, 16 consecutive queries). Window = [t-50, t+50] (101 wide).
// scores[q][r] = ( (q_t+u)·k_{t+r-50} + (q_t+v)·p_r ) / 8 ; softmax over r; o = sum attn*v
#define TQ 16
#define SR (TQ + 2*WHALF)   // 116 k/v rows staged

__global__ void __launch_bounds__(256)
attn_kernel(const float* __restrict__ q, const float* __restrict__ k,
            const float* __restrict__ v, const float* __restrict__ pc,
            const float* __restrict__ pu, const float* __restrict__ pv,
            float* __restrict__ o) {
    __shared__ __align__(16) float ks[SR * 65];   // k tile, later reused for v tile
    __shared__ float qu[TQ * 65];
    __shared__ float qv[TQ * 65];
    __shared__ float sc[TQ * 104];

    int b  = blockIdx.z;
    int h  = blockIdx.y;
    int t0 = blockIdx.x * TQ;
    int sbase = t0 - WHALF;
    int tid = threadIdx.x;

    // stage q (+u, +v)
    for (int e = tid; e < TQ * DKK; e += 256) {
        int qi = e >> 6, d = e & 63;
        int t = t0 + qi;
        float val = (t < TT) ? q[((size_t)(b * TT + t)) * CC + h * DKK + d] : 0.f;
        qu[qi * 65 + d] = val + pu[h * DKK + d];
        qv[qi * 65 + d] = val + pv[h * DKK + d];
    }
    // stage k
    for (int e = tid; e < SR * DKK; e += 256) {
        int si = e >> 6, d = e & 63;
        int s = sbase + si;
        ks[si * 65 + d] = (s >= 0 && s < TT)
            ? k[((size_t)(b * TT + s)) * CC + h * DKK + d] : 0.f;
    }
    __syncthreads();

    // scores (lane layout: qi fast so p-row loads are warp-uniform-ish)
    for (int e = tid; e < TQ * NR; e += 256) {
        int qi = e & 15;
        int r  = e >> 4;
        int t = t0 + qi;
        int s = t + r - WHALF;
        float out = -1e30f;
        if (t < TT && s >= 0 && s < TT) {
            const float* pr  = pc + (size_t)r * CC + h * DKK;
            const float* quR = &qu[qi * 65];
            const float* qvR = &qv[qi * 65];
            const float* kr  = &ks[(qi + r) * 65];
            float acc = 0.f;
            #pragma unroll 8
            for (int d = 0; d < DKK; d++)
                acc += quR[d] * kr[d] + qvR[d] * pr[d];
            out = acc * 0.125f;   // 1/sqrt(64)
        }
        sc[qi * 104 + r] = out;
    }
    __syncthreads();

    // stage v (overwrites ks) ; softmax in parallel on first 16 threads
    for (int e = tid; e < SR * DKK; e += 256) {
        int si = e >> 6, d = e & 63;
        int s = sbase + si;
        ks[si * 65 + d] = (s >= 0 && s < TT)
            ? v[((size_t)(b * TT + s)) * CC + h * DKK + d] : 0.f;
    }
    if (tid < TQ) {
        float* srow = &sc[tid * 104];
        float m = -1e30f;
        for (int r = 0; r < NR; r++) m = fmaxf(m, srow[r]);
        float sum = 0.f;
        for (int r = 0; r < NR; r++) { float ev = __expf(srow[r] - m); srow[r] = ev; sum += ev; }
        float inv = 1.f / sum;
        for (int r = 0; r < NR; r++) srow[r] *= inv;
    }
    __syncthreads();

    // o[t][d] = sum_r attn[r] * v[t+r-50][d]
    for (int e = tid; e < TQ * DKK; e += 256) {
        int qi = e >> 6, d = e & 63;
        int t = t0 + qi;
        if (t < TT) {
            const float* srow = &sc[qi * 104];
            const float* vr   = &ks[qi * 65 + d];
            float acc = 0.f;
            #pragma unroll 4
            for (int r = 0; r < NR; r++) acc += srow[r] * vr[r * 65];
            o[((size_t)(b * TT + t)) * CC + h * DKK + d] = acc;
        }
    }
}

// ---------------- driver ----------------
extern "C" void kernel_launch(void* const* d_in, const int* in_sizes, int n_in,
                              void* d_out, int out_size) {
    const float* x    = (const float*)d_in[0];
    const float* Wq   = (const float*)d_in[1];
    const float* bq   = (const float*)d_in[2];
    const float* Wk   = (const float*)d_in[3];
    const float* bk   = (const float*)d_in[4];
    const float* Wv   = (const float*)d_in[5];
    const float* bv   = (const float*)d_in[6];
    const float* Wo   = (const float*)d_in[7];
    const float* bo   = (const float*)d_in[8];
    const float* Wp   = (const float*)d_in[9];
    const float* pu   = (const float*)d_in[10];
    const float* pvv  = (const float*)d_in[11];
    const float* ln1g = (const float*)d_in[12];
    const float* ln1b = (const float*)d_in[13];
    const float* ln2g = (const float*)d_in[14];
    const float* ln2b = (const float*)d_in[15];
    const float* W1   = (const float*)d_in[16];
    const float* b1   = (const float*)d_in[17];
    const float* W2   = (const float*)d_in[18];
    const float* b2   = (const float*)d_in[19];
    // d_in[20] = att_mask: fixed band |i-j|>50, handled analytically.

    float *h, *y, *q, *k, *v, *o, *pe, *pc;
    cudaGetSymbolAddress((void**)&h,  g_h);
    cudaGetSymbolAddress((void**)&y,  g_y);
    cudaGetSymbolAddress((void**)&q,  g_q);
    cudaGetSymbolAddress((void**)&k,  g_k);
    cudaGetSymbolAddress((void**)&v,  g_v);
    cudaGetSymbolAddress((void**)&o,  g_o);
    cudaGetSymbolAddress((void**)&pe, g_pe);
    cudaGetSymbolAddress((void**)&pc, g_pc);

    init_h_kernel<<<(BT*CC + 255) / 256, 256>>>(x);
    pe_kernel<<<(NR*(CC/2) + 255) / 256, 256>>>();

    dim3 gBig(CC / GBN, (BT + GBM - 1) / GBM);  // (12, 32)
    dim3 gP  (CC / GBN, (NR + GBM - 1) / GBM);  // (12, 1)
    dim3 gAtt((TT + TQ - 1) / TQ, HH, BB);      // (63, 12, 4)

    for (int l = 0; l < LNUM; l++) {
        size_t wOff = (size_t)l * CC * CC;
        size_t bOff = (size_t)l * CC;

        ln_kernel<<<BT, 256>>>(h, y, ln1g + bOff, ln1b + bOff);
        sgemm_kernel<0><<<gBig, 256>>>(y, Wq + wOff, bq + bOff, nullptr, q, BT, CC, CC);
        sgemm_kernel<0><<<gBig, 256>>>(y, Wk + wOff, bk + bOff, nullptr, k, BT, CC, CC);
        sgemm_kernel<0><<<gBig, 256>>>(y, Wv + wOff, bv + bOff, nullptr, v, BT, CC, CC);
        sgemm_kernel<0><<<gP,   256>>>(pe, Wp + wOff, nullptr,  nullptr, pc, NR, CC, CC);
        attn_kernel<<<gAtt, 256>>>(q, k, v, pc, pu + bOff, pvv + bOff, o);
        sgemm_kernel<2><<<gBig, 256>>>(o, Wo + wOff, bo + bOff, h, h, BT, CC, CC);
        ln_kernel<<<BT, 256>>>(h, y, ln2g + bOff, ln2b + bOff);
        sgemm_kernel<1><<<gBig, 256>>>(y, W1 + wOff, b1 + bOff, nullptr, o, BT, CC, CC);
        float* outp = (l == LNUM - 1) ? (float*)d_out : h;
        sgemm_kernel<2><<<gBig, 256>>>(o, W2 + wOff, b2 + bOff, h, outp, BT, CC, CC);
    }
}

// round 5
// speedup vs baseline: 1.4637x; 1.4637x over previous
#include <cuda_runtime.h>
#include <math.h>
#include <stdint.h>

// ---------------- problem constants ----------------
#define LNUM 2
#define BB   4
#define TT   1000
#define CC   768
#define HH   12
#define DKK  64
#define WHALF 50         // band half-width (WIN//2)
#define NR   101         // relative positions actually reachable: -50..50
#define BT   (BB*TT)     // 4000 rows

// ---------------- device scratch (no allocs allowed) ----------------
__device__ float g_h[BT*CC];
__device__ float g_y[BT*CC];
__device__ float g_q[BT*CC];
__device__ float g_k[BT*CC];
__device__ float g_v[BT*CC];
__device__ float g_o[BT*CC];
__device__ float g_pe[NR*CC];   // central 101 rows of the rel-pos table
__device__ float g_pc[NR*CC];   // pe_cen @ Wp[l]

// ---------------- init: h = x * sqrt(C) ----------------
__global__ void init_h_kernel(const float* __restrict__ x) {
    int i = blockIdx.x * blockDim.x + threadIdx.x;
    if (i < BT*CC) g_h[i] = x[i] * 27.712812921102035f;  // sqrt(768)
}

// ---------------- positional table (central 101 rows only) ----------------
__global__ void pe_kernel() {
    int i = blockIdx.x * blockDim.x + threadIdx.x;
    if (i < NR*(CC/2)) {
        int r = i / (CC/2);
        int j = i % (CC/2);
        float div = expf(-(float)(2*j) * (9.210340371976184f / (float)CC)); // ln(10000)/C
        float ang = (float)(WHALF - r) * div;   // rel = -(r-50)
        g_pe[r*CC + 2*j]     = sinf(ang);
        g_pe[r*CC + 2*j + 1] = cosf(ang);
    }
}

// ---------------- LayerNorm (one block per row) ----------------
__global__ void ln_kernel(const float* __restrict__ in, float* __restrict__ out,
                          const float* __restrict__ g, const float* __restrict__ b) {
    int row = blockIdx.x;
    const float* xr = in + (size_t)row * CC;
    float s = 0.f, s2 = 0.f;
    for (int i = threadIdx.x; i < CC; i += 256) {
        float v = xr[i];
        s += v; s2 += v * v;
    }
    __shared__ float sh[16];
    #pragma unroll
    for (int o = 16; o; o >>= 1) {
        s  += __shfl_xor_sync(0xffffffffu, s,  o);
        s2 += __shfl_xor_sync(0xffffffffu, s2, o);
    }
    int w = threadIdx.x >> 5;
    if ((threadIdx.x & 31) == 0) { sh[w] = s; sh[8 + w] = s2; }
    __syncthreads();
    s = 0.f; s2 = 0.f;
    #pragma unroll
    for (int i = 0; i < 8; i++) { s += sh[i]; s2 += sh[8 + i]; }
    float mean = s * (1.f / CC);
    float var  = s2 * (1.f / CC) - mean * mean;
    float rstd = rsqrtf(var + 1e-5f);
    float* orow = out + (size_t)row * CC;
    for (int i = threadIdx.x; i < CC; i += 256)
        orow[i] = (xr[i] - mean) * rstd * g[i] + b[i];
}

// ---------------- tf32 tensor-core GEMM ----------------
// C(MxN) = A(MxK) @ B(KxN) [+bias] [epilogue], fp32 accumulate, tf32 inputs.
// BM=128, BN=64, BK=16. 128 threads = 4 warps in 2x2 grid; warp tile 64x32.
// Smem holds PRE-PACKED mma fragments (conflict-free STS and LDS):
//   Asf[buf][mt*2+ch][lane*4 + reg]  (uint4 per lane = {a0,a1,a2,a3})
//   Bsf[buf][nt*2+ch][lane*2 + reg]  (uint2 per lane = {b0,b1})
// EPI: 0 = none, 1 = gelu(tanh), 2 = += resid

__device__ __forceinline__ uint32_t f2tf32(float x) {
    uint32_t u;
    asm("cvt.rna.tf32.f32 %0, %1;" : "=r"(u) : "f"(x));
    return u;
}

__device__ __forceinline__ void mma_tf32(float c[4], const uint4& a, const uint2& b) {
    asm volatile(
        "mma.sync.aligned.m16n8k8.row.col.f32.tf32.tf32.f32 "
        "{%0,%1,%2,%3}, {%4,%5,%6,%7}, {%8,%9}, {%0,%1,%2,%3};"
        : "+f"(c[0]), "+f"(c[1]), "+f"(c[2]), "+f"(c[3])
        : "r"(a.x), "r"(a.y), "r"(a.z), "r"(a.w), "r"(b.x), "r"(b.y));
}

__device__ __forceinline__ float gelu_f(float x) {
    float x3 = x * x * x;
    return 0.5f * x * (1.f + tanhf(0.7978845608028654f * (x + 0.044715f * x3)));
}

template<int EPI>
__global__ void __launch_bounds__(128)
tgemm_kernel(const float* __restrict__ A, const float* __restrict__ Bm,
             const float* __restrict__ bias, const float* __restrict__ resid,
             float* __restrict__ Cm, int M, int N, int K) {
    __shared__ uint32_t Asf[2][16][128];   // 16 KB
    __shared__ uint32_t Bsf[2][16][64];    //  8 KB

    const int tid  = threadIdx.x;
    const int warp = tid >> 5;
    const int lane = tid & 31;
    const int g    = lane >> 2;    // 0..7
    const int t    = lane & 3;     // 0..3
    const int wr   = warp >> 1;    // 0..1 : warp row (64 M-rows each)
    const int wc   = warp & 1;     // 0..1 : warp col (32 N-cols each)
    const int row0 = blockIdx.y * 128;
    const int col0 = blockIdx.x * 64;

    float acc[4][4][4];
    #pragma unroll
    for (int i = 0; i < 4; i++)
        #pragma unroll
        for (int j = 0; j < 4; j++)
            #pragma unroll
            for (int r = 0; r < 4; r++) acc[i][j][r] = 0.f;

    uint32_t ra[4][4];
    uint32_t rb[4][2];

    // Each warp produces fragment groups [warp*4, warp*4+4).
    // Group grp: mt = grp>>1 (A) / nt = grp>>1 (B), ch = grp&1 (k8 chunk).
#define LOAD_TILES(k0) do {                                                          \
        _Pragma("unroll")                                                            \
        for (int q2 = 0; q2 < 4; q2++) {                                             \
            int grp = warp * 4 + q2;                                                 \
            int mt = grp >> 1, ch = grp & 1;                                         \
            int m0 = mt * 16 + g;                                                    \
            const float* ab = A + (size_t)(row0 + m0) * K + (k0) + ch * 8 + t;       \
            bool v0 = (row0 + m0)     < M;                                           \
            bool v1 = (row0 + m0 + 8) < M;                                           \
            ra[q2][0] = f2tf32(v0 ? ab[0] : 0.f);                                    \
            ra[q2][1] = f2tf32(v1 ? ab[(size_t)8 * K] : 0.f);                        \
            ra[q2][2] = f2tf32(v0 ? ab[4] : 0.f);                                    \
            ra[q2][3] = f2tf32(v1 ? ab[(size_t)8 * K + 4] : 0.f);                    \
            const float* bb = Bm + (size_t)((k0) + ch * 8 + t) * N + col0 + mt * 8 + g; \
            rb[q2][0] = f2tf32(bb[0]);                                               \
            rb[q2][1] = f2tf32(bb[(size_t)4 * N]);                                   \
        }                                                                            \
    } while (0)

    LOAD_TILES(0);
    const int steps = K >> 4;
    for (int s = 0; s < steps; s++) {
        const int buf = s & 1;
        #pragma unroll
        for (int q2 = 0; q2 < 4; q2++) {
            *(uint4*)&Asf[buf][warp * 4 + q2][lane * 4] =
                make_uint4(ra[q2][0], ra[q2][1], ra[q2][2], ra[q2][3]);
            *(uint2*)&Bsf[buf][warp * 4 + q2][lane * 2] =
                make_uint2(rb[q2][0], rb[q2][1]);
        }
        __syncthreads();
        if (s + 1 < steps) LOAD_TILES((s + 1) * 16);
        #pragma unroll
        for (int ch = 0; ch < 2; ch++) {
            uint4 af[4];
            uint2 bf[4];
            #pragma unroll
            for (int i = 0; i < 4; i++)
                af[i] = *(const uint4*)&Asf[buf][(wr * 4 + i) * 2 + ch][lane * 4];
            #pragma unroll
            for (int j = 0; j < 4; j++)
                bf[j] = *(const uint2*)&Bsf[buf][(wc * 4 + j) * 2 + ch][lane * 2];
            #pragma unroll
            for (int i = 0; i < 4; i++)
                #pragma unroll
                for (int j = 0; j < 4; j++)
                    mma_tf32(acc[i][j], af[i], bf[j]);
        }
    }
#undef LOAD_TILES

    // epilogue: c0/c1 at (row g, cols 2t/2t+1), c2/c3 at row g+8
    #pragma unroll
    for (int i = 0; i < 4; i++) {
        int rbase = row0 + wr * 64 + i * 16 + g;
        #pragma unroll
        for (int j = 0; j < 4; j++) {
            int col = col0 + wc * 32 + j * 8 + t * 2;
            float bx = 0.f, by = 0.f;
            if (bias) { bx = bias[col]; by = bias[col + 1]; }
            #pragma unroll
            for (int hh = 0; hh < 2; hh++) {
                int row = rbase + hh * 8;
                if (row < M) {
                    float c0 = acc[i][j][hh * 2 + 0] + bx;
                    float c1 = acc[i][j][hh * 2 + 1] + by;
                    if (EPI == 1) { c0 = gelu_f(c0); c1 = gelu_f(c1); }
                    if (EPI == 2) {
                        float2 rv = *(const float2*)(resid + (size_t)row * N + col);
                        c0 += rv.x; c1 += rv.y;
                    }
                    *(float2*)(Cm + (size_t)row * N + col) = make_float2(c0, c1);
                }
            }
        }
    }
}

// ---------------- banded rel-pos attention ----------------
#define TQ 16
#define SR (TQ + 2*WHALF)   // 116 k/v rows staged

__global__ void __launch_bounds__(256)
attn_kernel(const float* __restrict__ q, const float* __restrict__ k,
            const float* __restrict__ v, const float* __restrict__ pc,
            const float* __restrict__ pu, const float* __restrict__ pv,
            float* __restrict__ o) {
    __shared__ __align__(16) float ks[SR * 65];   // k tile, later reused for v tile
    __shared__ float qu[TQ * 65];
    __shared__ float qv[TQ * 65];
    __shared__ float sc[TQ * 104];

    int b  = blockIdx.z;
    int h  = blockIdx.y;
    int t0 = blockIdx.x * TQ;
    int sbase = t0 - WHALF;
    int tid = threadIdx.x;

    for (int e = tid; e < TQ * DKK; e += 256) {
        int qi = e >> 6, d = e & 63;
        int t = t0 + qi;
        float val = (t < TT) ? q[((size_t)(b * TT + t)) * CC + h * DKK + d] : 0.f;
        qu[qi * 65 + d] = val + pu[h * DKK + d];
        qv[qi * 65 + d] = val + pv[h * DKK + d];
    }
    for (int e = tid; e < SR * DKK; e += 256) {
        int si = e >> 6, d = e & 63;
        int s = sbase + si;
        ks[si * 65 + d] = (s >= 0 && s < TT)
            ? k[((size_t)(b * TT + s)) * CC + h * DKK + d] : 0.f;
    }
    __syncthreads();

    for (int e = tid; e < TQ * NR; e += 256) {
        int qi = e & 15;
        int r  = e >> 4;
        int t = t0 + qi;
        int s = t + r - WHALF;
        float out = -1e30f;
        if (t < TT && s >= 0 && s < TT) {
            const float* pr  = pc + (size_t)r * CC + h * DKK;
            const float* quR = &qu[qi * 65];
            const float* qvR = &qv[qi * 65];
            const float* kr  = &ks[(qi + r) * 65];
            float acc = 0.f;
            #pragma unroll 8
            for (int d = 0; d < DKK; d++)
                acc += quR[d] * kr[d] + qvR[d] * pr[d];
            out = acc * 0.125f;
        }
        sc[qi * 104 + r] = out;
    }
    __syncthreads();

    for (int e = tid; e < SR * DKK; e += 256) {
        int si = e >> 6, d = e & 63;
        int s = sbase + si;
        ks[si * 65 + d] = (s >= 0 && s < TT)
            ? v[((size_t)(b * TT + s)) * CC + h * DKK + d] : 0.f;
    }
    if (tid < TQ) {
        float* srow = &sc[tid * 104];
        float m = -1e30f;
        for (int r = 0; r < NR; r++) m = fmaxf(m, srow[r]);
        float sum = 0.f;
        for (int r = 0; r < NR; r++) { float ev = __expf(srow[r] - m); srow[r] = ev; sum += ev; }
        float inv = 1.f / sum;
        for (int r = 0; r < NR; r++) srow[r] *= inv;
    }
    __syncthreads();

    for (int e = tid; e < TQ * DKK; e += 256) {
        int qi = e >> 6, d = e & 63;
        int t = t0 + qi;
        if (t < TT) {
            const float* srow = &sc[qi * 104];
            const float* vr   = &ks[qi * 65 + d];
            float acc = 0.f;
            #pragma unroll 4
            for (int r = 0; r < NR; r++) acc += srow[r] * vr[r * 65];
            o[((size_t)(b * TT + t)) * CC + h * DKK + d] = acc;
        }
    }
}

// ---------------- driver ----------------
extern "C" void kernel_launch(void* const* d_in, const int* in_sizes, int n_in,
                              void* d_out, int out_size) {
    const float* x    = (const float*)d_in[0];
    const float* Wq   = (const float*)d_in[1];
    const float* bq   = (const float*)d_in[2];
    const float* Wk   = (const float*)d_in[3];
    const float* bk   = (const float*)d_in[4];
    const float* Wv   = (const float*)d_in[5];
    const float* bv   = (const float*)d_in[6];
    const float* Wo   = (const float*)d_in[7];
    const float* bo   = (const float*)d_in[8];
    const float* Wp   = (const float*)d_in[9];
    const float* pu   = (const float*)d_in[10];
    const float* pvv  = (const float*)d_in[11];
    const float* ln1g = (const float*)d_in[12];
    const float* ln1b = (const float*)d_in[13];
    const float* ln2g = (const float*)d_in[14];
    const float* ln2b = (const float*)d_in[15];
    const float* W1   = (const float*)d_in[16];
    const float* b1   = (const float*)d_in[17];
    const float* W2   = (const float*)d_in[18];
    const float* b2   = (const float*)d_in[19];
    // d_in[20] = att_mask: fixed band |i-j|>50, handled analytically.

    float *h, *y, *q, *k, *v, *o, *pe, *pc;
    cudaGetSymbolAddress((void**)&h,  g_h);
    cudaGetSymbolAddress((void**)&y,  g_y);
    cudaGetSymbolAddress((void**)&q,  g_q);
    cudaGetSymbolAddress((void**)&k,  g_k);
    cudaGetSymbolAddress((void**)&v,  g_v);
    cudaGetSymbolAddress((void**)&o,  g_o);
    cudaGetSymbolAddress((void**)&pe, g_pe);
    cudaGetSymbolAddress((void**)&pc, g_pc);

    init_h_kernel<<<(BT*CC + 255) / 256, 256>>>(x);
    pe_kernel<<<(NR*(CC/2) + 255) / 256, 256>>>();

    dim3 gBig(CC / 64, (BT + 127) / 128);   // (12, 32)
    dim3 gP  (CC / 64, 1);                  // (12, 1), M=101
    dim3 gAtt((TT + TQ - 1) / TQ, HH, BB);  // (63, 12, 4)

    for (int l = 0; l < LNUM; l++) {
        size_t wOff = (size_t)l * CC * CC;
        size_t bOff = (size_t)l * CC;

        ln_kernel<<<BT, 256>>>(h, y, ln1g + bOff, ln1b + bOff);
        tgemm_kernel<0><<<gBig, 128>>>(y, Wq + wOff, bq + bOff, nullptr, q, BT, CC, CC);
        tgemm_kernel<0><<<gBig, 128>>>(y, Wk + wOff, bk + bOff, nullptr, k, BT, CC, CC);
        tgemm_kernel<0><<<gBig, 128>>>(y, Wv + wOff, bv + bOff, nullptr, v, BT, CC, CC);
        tgemm_kernel<0><<<gP,   128>>>(pe, Wp + wOff, nullptr,  nullptr, pc, NR, CC, CC);
        attn_kernel<<<gAtt, 256>>>(q, k, v, pc, pu + bOff, pvv + bOff, o);
        tgemm_kernel<2><<<gBig, 128>>>(o, Wo + wOff, bo + bOff, h, h, BT, CC, CC);
        ln_kernel<<<BT, 256>>>(h, y, ln2g + bOff, ln2b + bOff);
        tgemm_kernel<1><<<gBig, 128>>>(y, W1 + wOff, b1 + bOff, nullptr, o, BT, CC, CC);
        float* outp = (l == LNUM - 1) ? (float*)d_out : h;
        tgemm_kernel<2><<<gBig, 128>>>(o, W2 + wOff, b2 + bOff, h, outp, BT, CC, CC);
    }
}